// round 14
// baseline (speedup 1.0000x reference)
#include <cuda_runtime.h>
#include <math.h>

#define Bn 32
#define Ln 1024
#define Hn 12
#define DV 64
#define MN 128
#define HDIM 768
#define BH (Bn*Hn)
#define TOK (Bn*Ln)
#define PIT 132

// ---------------- device scratch ----------------
__device__ float g_q  [BH*Ln*DV];
__device__ float g_v  [BH*Ln*DV];
__device__ float g_phi[BH*Ln*MN];
__device__ float g_om [Hn*DV*64];
__device__ float g_amp[Hn];
__device__ float g_G  [BH*MN*MN];
__device__ float g_C  [BH*MN*DV];
__device__ float g_P  [BH*MN*MN];
__device__ float g_W  [BH*MN*DV];
__device__ float g_sf [TOK*HDIM];
__device__ float g_klbh[BH];

__device__ __forceinline__ float blk_sum(float v, float* red) {
    int tid = threadIdx.x;
#pragma unroll
    for (int o = 16; o; o >>= 1) v += __shfl_xor_sync(0xffffffffu, v, o);
    __syncthreads();
    if ((tid & 31) == 0) red[tid >> 5] = v;
    __syncthreads();
    if (tid < 32) {
        float r = (tid < 8) ? red[tid] : 0.0f;
#pragma unroll
        for (int o = 4; o; o >>= 1) r += __shfl_xor_sync(0xffffffffu, r, o);
        if (tid == 0) red[0] = r;
    }
    __syncthreads();
    return red[0];
}

// ---------------- tf32 helpers ----------------
__device__ __forceinline__ unsigned tf32_of(float x) {
    unsigned u;
    asm("cvt.rna.tf32.f32 %0, %1;" : "=r"(u) : "f"(x));
    return u;
}
__device__ __forceinline__ void mma_tf32(float* d, const unsigned* a, const unsigned* b) {
    asm("mma.sync.aligned.m16n8k8.row.col.f32.tf32.tf32.f32 "
        "{%0,%1,%2,%3},{%4,%5,%6,%7},{%8,%9},{%0,%1,%2,%3};"
        : "+f"(d[0]), "+f"(d[1]), "+f"(d[2]), "+f"(d[3])
        : "r"(a[0]), "r"(a[1]), "r"(a[2]), "r"(a[3]), "r"(b[0]), "r"(b[1]));
}

// ---------------- K0 ----------------
__global__ void k0_prep(const float* __restrict__ log_sf,
                        const float* __restrict__ log_ls,
                        const float* __restrict__ omega_half) {
    int idx = blockIdx.x * blockDim.x + threadIdx.x;
    const int NOM = Hn * DV * 64;
    if (idx < NOM) {
        int h = idx / (DV * 64);
        int d = (idx / 64) % DV;
        float scale = 1.41421356237309515f * expf(-log_ls[h * DV + d]);
        g_om[idx] = omega_half[idx] * scale;
    }
    if (idx < Hn) g_amp[idx] = sqrtf(expf(log_sf[idx]));
}

// ---------------- gemm768_tc: out = A[rows,768] @ Wm[cols,768]^T via 3xTF32 ----------------
#define SSTR 136
__global__ void __launch_bounds__(256) gemm768_tc(const float* __restrict__ Ain,
                                                  const float* __restrict__ Wm,
                                                  int mode,
                                                  const float* __restrict__ bias,
                                                  float* __restrict__ out) {
    extern __shared__ unsigned sm4[];
    unsigned* Ah = sm4;
    unsigned* Al = Ah + 32 * SSTR;
    unsigned* Bh = Al + 32 * SSTR;
    unsigned* Bl = Bh + 32 * SSTR;
    const float* A = (mode == 0) ? Ain : (const float*)g_sf;
    int cx = blockIdx.x, ry = blockIdx.y;
    int tid = threadIdx.x, lane = tid & 31, wid = tid >> 5;
    int m0 = (wid & 3) * 32, n0 = (wid >> 2) * 64;
    int lrow = tid >> 1, lkb = (tid & 1) * 16;
    const float* ap = A  + (size_t)(ry * 128 + lrow) * HDIM + lkb;
    const float* bp = Wm + (size_t)(cx * 128 + lrow) * HDIM + lkb;

    float acc[2][8][4];
#pragma unroll
    for (int i = 0; i < 2; i++)
#pragma unroll
        for (int j = 0; j < 8; j++)
#pragma unroll
            for (int k = 0; k < 4; k++) acc[i][j][k] = 0.0f;

    float av[16], wv[16];
#pragma unroll
    for (int g = 0; g < 4; g++) {
        *(float4*)&av[g * 4] = *(const float4*)(ap + g * 4);
        *(float4*)&wv[g * 4] = *(const float4*)(bp + g * 4);
    }

    for (int c = 0; c < 24; c++) {
        __syncthreads();
#pragma unroll
        for (int i = 0; i < 16; i++) {
            unsigned h = tf32_of(av[i]);
            Ah[(lkb + i) * SSTR + lrow] = h;
            Al[(lkb + i) * SSTR + lrow] = tf32_of(av[i] - __uint_as_float(h));
            unsigned hb = tf32_of(wv[i]);
            Bh[(lkb + i) * SSTR + lrow] = hb;
            Bl[(lkb + i) * SSTR + lrow] = tf32_of(wv[i] - __uint_as_float(hb));
        }
        __syncthreads();
        if (c + 1 < 24) {
            const float* a2 = ap + (c + 1) * 32;
            const float* b2 = bp + (c + 1) * 32;
#pragma unroll
            for (int g = 0; g < 4; g++) {
                *(float4*)&av[g * 4] = *(const float4*)(a2 + g * 4);
                *(float4*)&wv[g * 4] = *(const float4*)(b2 + g * 4);
            }
        }
        int r = lane >> 2, q = lane & 3;
#pragma unroll
        for (int ks = 0; ks < 4; ks++) {
            int kc = ks * 8;
            unsigned ahi[2][4], alo[2][4];
#pragma unroll
            for (int mt = 0; mt < 2; mt++) {
                int mr = m0 + mt * 16 + r;
                ahi[mt][0] = Ah[(kc + q) * SSTR + mr];
                ahi[mt][1] = Ah[(kc + q) * SSTR + mr + 8];
                ahi[mt][2] = Ah[(kc + q + 4) * SSTR + mr];
                ahi[mt][3] = Ah[(kc + q + 4) * SSTR + mr + 8];
                alo[mt][0] = Al[(kc + q) * SSTR + mr];
                alo[mt][1] = Al[(kc + q) * SSTR + mr + 8];
                alo[mt][2] = Al[(kc + q + 4) * SSTR + mr];
                alo[mt][3] = Al[(kc + q + 4) * SSTR + mr + 8];
            }
#pragma unroll
            for (int nt = 0; nt < 8; nt++) {
                int nc = n0 + nt * 8 + r;
                unsigned bhi[2] = {Bh[(kc + q) * SSTR + nc], Bh[(kc + q + 4) * SSTR + nc]};
                unsigned blo[2] = {Bl[(kc + q) * SSTR + nc], Bl[(kc + q + 4) * SSTR + nc]};
#pragma unroll
                for (int mt = 0; mt < 2; mt++) {
                    mma_tf32(acc[mt][nt], ahi[mt], bhi);
                    mma_tf32(acc[mt][nt], ahi[mt], blo);
                    mma_tf32(acc[mt][nt], alo[mt], bhi);
                }
            }
        }
    }

    int r = lane >> 2, q = lane & 3;
#pragma unroll
    for (int mt = 0; mt < 2; mt++) {
#pragma unroll
        for (int nt = 0; nt < 8; nt++) {
            int cl = n0 + nt * 8 + 2 * q;
#pragma unroll
            for (int half = 0; half < 2; half++) {
                int row = ry * 128 + m0 + mt * 16 + r + half * 8;
                float c0 = acc[mt][nt][half * 2], c1 = acc[mt][nt][half * 2 + 1];
                if (mode == 0) {
                    int b = row >> 10, l = row & 1023;
                    size_t base = ((size_t)(b * Hn + cx) * Ln + l) * DV;
                    if (cl < 64) *(float2*)&g_q[base + cl]      = make_float2(c0, c1);
                    else         *(float2*)&g_v[base + cl - 64] = make_float2(c0, c1);
                } else {
                    int col = cx * 128 + cl;
                    *(float2*)&out[(size_t)row * HDIM + col] =
                        make_float2(c0 + bias[col], c1 + bias[col + 1]);
                }
            }
        }
    }
}

// ---------------- K2: phi (fast sincos) ----------------
__global__ void __launch_bounds__(256) k2_phi(const float* __restrict__ phase) {
    __shared__ float qs[64][64];
    __shared__ float oms[64][64];
    int l0 = blockIdx.x * 64;
    int bh = blockIdx.y;
    int h  = bh % Hn;
    int tid = threadIdx.x;
    int tx = tid & 15, ty = tid >> 4;
    int r = tid >> 2;
    int cbase = (tid & 3) * 16;
    const float* qrow = g_q + ((size_t)bh * Ln + l0 + r) * DV;
    const float* orow = g_om + (size_t)h * DV * 64 + r * 64;
#pragma unroll
    for (int c = 0; c < 4; c++) {
        float4 qv4 = *(const float4*)(qrow + cbase + c * 4);
        qs[cbase + c*4 + 0][r] = qv4.x; qs[cbase + c*4 + 1][r] = qv4.y;
        qs[cbase + c*4 + 2][r] = qv4.z; qs[cbase + c*4 + 3][r] = qv4.w;
        *(float4*)&oms[r][cbase + c * 4] = *(const float4*)(orow + cbase + c * 4);
    }
    __syncthreads();
    float acc[4][4] = {};
#pragma unroll
    for (int kk = 0; kk < 64; kk++) {
        float4 a = *(const float4*)&qs[kk][ty * 4];
        float4 b = *(const float4*)&oms[kk][tx * 4];
        acc[0][0] += a.x*b.x; acc[0][1] += a.x*b.y; acc[0][2] += a.x*b.z; acc[0][3] += a.x*b.w;
        acc[1][0] += a.y*b.x; acc[1][1] += a.y*b.y; acc[1][2] += a.y*b.z; acc[1][3] += a.y*b.w;
        acc[2][0] += a.z*b.x; acc[2][1] += a.z*b.y; acc[2][2] += a.z*b.z; acc[2][3] += a.z*b.w;
        acc[3][0] += a.w*b.x; acc[3][1] += a.w*b.y; acc[3][2] += a.w*b.z; acc[3][3] += a.w*b.w;
    }
    float sc = g_amp[h] * 0.08838834764831845f;
#pragma unroll
    for (int i = 0; i < 4; i++) {
        int l = l0 + ty * 4 + i;
        float* pb = g_phi + ((size_t)bh * Ln + l) * MN;
#pragma unroll
        for (int j = 0; j < 4; j++) {
            int m = tx * 4 + j;
            float p = acc[i][j] + phase[h * 64 + m];
            float s, c;
            __sincosf(p, &s, &c);
            pb[m]      = sc * c;
            pb[m + 64] = sc * s;
        }
    }
}

// ---------------- K3 (tensor): [G|C] = phi^T [phi|v] via 3xTF32 MMA ----------------
#define VSTR 72
__global__ void __launch_bounds__(256) k3_tc() {
    __shared__ unsigned ph[16 * SSTR], pl[16 * SSTR];
    __shared__ unsigned vh[16 * VSTR], vl[16 * VSTR];
    int bh = blockIdx.x;
    int tid = threadIdx.x, lane = tid & 31, wid = tid >> 5;
    int m0 = (wid & 3) * 32, n0 = (wid >> 2) * 96;
    const float* phib = g_phi + (size_t)bh * Ln * MN;
    const float* vb   = g_v   + (size_t)bh * Ln * DV;
    float acc[2][12][4] = {};

    int lr = tid >> 4, mc = (tid & 15) * 8;   // phi loader
    int vr_ = tid >> 4, vc = (tid & 15) * 4;  // v loader
    int r = lane >> 2, q = lane & 3;

    for (int s = 0; s < 64; s++) {
        int l0 = s * 16;
        const float* pr = phib + (size_t)(l0 + lr) * MN + mc;
        float4 p0 = *(const float4*)pr;
        float4 p1 = *(const float4*)(pr + 4);
        float4 vv = *(const float4*)(vb + (size_t)(l0 + vr_) * DV + vc);
        __syncthreads();
        float pe[8] = {p0.x, p0.y, p0.z, p0.w, p1.x, p1.y, p1.z, p1.w};
#pragma unroll
        for (int i = 0; i < 8; i++) {
            unsigned hi = tf32_of(pe[i]);
            ph[lr * SSTR + mc + i] = hi;
            pl[lr * SSTR + mc + i] = tf32_of(pe[i] - __uint_as_float(hi));
        }
        float ve[4] = {vv.x, vv.y, vv.z, vv.w};
#pragma unroll
        for (int i = 0; i < 4; i++) {
            unsigned hi = tf32_of(ve[i]);
            vh[vr_ * VSTR + vc + i] = hi;
            vl[vr_ * VSTR + vc + i] = tf32_of(ve[i] - __uint_as_float(hi));
        }
        __syncthreads();
#pragma unroll
        for (int ks = 0; ks < 2; ks++) {
            int kc = ks * 8;
            unsigned ah[2][4], al[2][4];
#pragma unroll
            for (int mt = 0; mt < 2; mt++) {
                int mr = m0 + mt * 16 + r;
                ah[mt][0] = ph[(kc + q) * SSTR + mr];
                ah[mt][1] = ph[(kc + q) * SSTR + mr + 8];
                ah[mt][2] = ph[(kc + q + 4) * SSTR + mr];
                ah[mt][3] = ph[(kc + q + 4) * SSTR + mr + 8];
                al[mt][0] = pl[(kc + q) * SSTR + mr];
                al[mt][1] = pl[(kc + q) * SSTR + mr + 8];
                al[mt][2] = pl[(kc + q + 4) * SSTR + mr];
                al[mt][3] = pl[(kc + q + 4) * SSTR + mr + 8];
            }
#pragma unroll
            for (int nt = 0; nt < 12; nt++) {
                int nc = n0 + nt * 8 + r;
                unsigned b_h[2], b_l[2];
                if (nc < 128) {
                    b_h[0] = ph[(kc + q) * SSTR + nc];
                    b_h[1] = ph[(kc + q + 4) * SSTR + nc];
                    b_l[0] = pl[(kc + q) * SSTR + nc];
                    b_l[1] = pl[(kc + q + 4) * SSTR + nc];
                } else {
                    int c2 = nc - 128;
                    b_h[0] = vh[(kc + q) * VSTR + c2];
                    b_h[1] = vh[(kc + q + 4) * VSTR + c2];
                    b_l[0] = vl[(kc + q) * VSTR + c2];
                    b_l[1] = vl[(kc + q + 4) * VSTR + c2];
                }
#pragma unroll
                for (int mt = 0; mt < 2; mt++) {
                    mma_tf32(acc[mt][nt], ah[mt], b_h);
                    mma_tf32(acc[mt][nt], ah[mt], b_l);
                    mma_tf32(acc[mt][nt], al[mt], b_h);
                }
            }
        }
    }

    float* Gb = g_G + (size_t)bh * MN * MN;
    float* Cb = g_C + (size_t)bh * MN * DV;
#pragma unroll
    for (int mt = 0; mt < 2; mt++)
#pragma unroll
        for (int nt = 0; nt < 12; nt++) {
            int n = n0 + nt * 8 + 2 * q;
#pragma unroll
            for (int half = 0; half < 2; half++) {
                int m = m0 + mt * 16 + r + half * 8;
                float c0 = acc[mt][nt][half * 2], c1 = acc[mt][nt][half * 2 + 1];
                if (n < 128) *(float2*)&Gb[(size_t)m * MN + n]        = make_float2(c0, c1);
                else         *(float2*)&Cb[(size_t)m * DV + (n - 128)] = make_float2(c0, c1);
            }
        }
}

// ---------------- K4 (Gauss-Jordan inverse, fully parallel) ----------------
__global__ void __launch_bounds__(256) k4_gj(const float* __restrict__ log_sigma2) {
    extern __shared__ float sm[];
    float* sA   = sm;                  // 128 x PIT
    float* sC   = sm + 128 * PIT;      // 128 x 64
    float* rowj = sC + 8192;           // 128
    float* colj = rowj + 128;          // 128
    float* sPiv = colj + 128;          // 128
    __shared__ float red[8];
    __shared__ float sp;
    int bh = blockIdx.x;
    int tid = threadIdx.x;
    float sigma2 = expf(log_sigma2[0]);

    for (int i = tid; i < 16384; i += 256) {
        int r = i >> 7, c = i & 127;
        float v = g_G[(size_t)bh * 16384 + i];
        if (r == c) v += sigma2 + 1e-6f;
        sA[r * PIT + c] = v;
    }
    for (int i = tid; i < 8192; i += 256) sC[i] = g_C[(size_t)bh * 8192 + i];
    __syncthreads();

    int mi = tid >> 1;
    int kb = (tid & 1) * 64;
    for (int j = 0; j < 128; j++) {
        if (tid < 128) {
            rowj[tid] = sA[j * PIT + tid];
            colj[tid] = sA[tid * PIT + j];
        }
        if (tid == 0) { float d = sA[j * PIT + j]; sPiv[j] = d; sp = 1.0f / d; }
        __syncthreads();
        float p = sp;
        if (mi == j) {
#pragma unroll
            for (int c = 0; c < 64; c += 4) {
                int k = kb + c;
                float4 rv = *(float4*)&rowj[k];
                float4 o = make_float4(rv.x * p, rv.y * p, rv.z * p, rv.w * p);
                if (j >= k && j < k + 4) {
                    if (j == k) o.x = p; else if (j == k+1) o.y = p;
                    else if (j == k+2) o.z = p; else o.w = p;
                }
                *(float4*)&sA[j * PIT + k] = o;
            }
        } else {
            float ci = colj[mi] * p;
#pragma unroll
            for (int c = 0; c < 64; c += 4) {
                int k = kb + c;
                float4 av = *(float4*)&sA[mi * PIT + k];
                float4 rv = *(float4*)&rowj[k];
                float4 o = make_float4(av.x - ci * rv.x, av.y - ci * rv.y,
                                       av.z - ci * rv.z, av.w - ci * rv.w);
                if (j >= k && j < k + 4) {
                    float nv = -ci;
                    if (j == k) o.x = nv; else if (j == k+1) o.y = nv;
                    else if (j == k+2) o.z = nv; else o.w = nv;
                }
                *(float4*)&sA[mi * PIT + k] = o;
            }
        }
        __syncthreads();
    }

    float ld = (tid < 128) ? logf(sPiv[tid]) : 0.0f;
    float logdetA = blk_sum(ld, red);
    float tr = (tid < 128) ? sA[tid * PIT + tid] : 0.0f;
    float tr_Ainv = blk_sum(tr, red);

    float mu = 0.0f;
    for (int g = tid; g < 2048; g += 256) {
        int m = g >> 4, d4 = (g & 15) * 4;
        float4 a = make_float4(0.f, 0.f, 0.f, 0.f);
        for (int k = 0; k < 128; k++) {
            float pm = sA[m * PIT + k];
            float4 cv = *(float4*)&sC[k * 64 + d4];
            a.x += pm * cv.x; a.y += pm * cv.y; a.z += pm * cv.z; a.w += pm * cv.w;
        }
        *(float4*)&g_W[(size_t)bh * 8192 + m * 64 + d4] = a;
        mu += a.x * a.x + a.y * a.y + a.z * a.z + a.w * a.w;
    }
    float mu_norm2 = blk_sum(mu, red);

    for (int i = tid; i < 16384; i += 256) {
        int r = i >> 7, c = i & 127;
        g_P[(size_t)bh * 16384 + i] = sA[r * PIT + c];
    }

    if (tid == 0) {
        float kl = 0.5f * (64.0f * sigma2 * tr_Ainv + mu_norm2 - 8192.0f
                           - 64.0f * (128.0f * logf(sigma2) - logdetA));
        g_klbh[bh] = kl;
    }
}

// ---------------- K56: Y = phi @ [P|W]; var; samples ----------------
__global__ void __launch_bounds__(256) k56_mean(const float* __restrict__ log_sigma2,
                                               const float* __restrict__ eps) {
    extern __shared__ float sm[];
    float* sPW = sm;            // 128x192
    float* sph = sm + 24576;    // 128x64 (m-major)
    int lq = blockIdx.x, bh = blockIdx.y;
    int b = bh / Hn, h = bh % Hn;
    int tid = threadIdx.x;
    int tx = tid & 15, ty = tid >> 4;
    float sigma2 = expf(log_sigma2[0]);
    const float* Pb = g_P + (size_t)bh * 16384;
    const float* Wb = g_W + (size_t)bh * 8192;

#pragma unroll
    for (int qq = 0; qq < 24; qq++) {
        int w = (tid + 256 * qq) * 4;
        int k = w / 192, c = w - k * 192;
        float4 val = (c < 128) ? *(const float4*)(Pb + k * 128 + c)
                               : *(const float4*)(Wb + k * 64 + (c - 128));
        *(float4*)(sPW + w) = val;
    }

    int pl = tid & 63, pm = (tid >> 6) * 32;
    for (int t4 = 0; t4 < 4; t4++) {
        __syncthreads();
        int l0 = lq * 256 + t4 * 64;
        const float* prow = g_phi + ((size_t)bh * Ln + l0 + pl) * MN + pm;
#pragma unroll
        for (int e = 0; e < 8; e++) {
            float4 pv = *(const float4*)(prow + e * 4);
            sph[(pm + e*4 + 0) * 64 + pl] = pv.x;
            sph[(pm + e*4 + 1) * 64 + pl] = pv.y;
            sph[(pm + e*4 + 2) * 64 + pl] = pv.z;
            sph[(pm + e*4 + 3) * 64 + pl] = pv.w;
        }
        __syncthreads();

        float acc[4][12] = {};
#pragma unroll 8
        for (int kk = 0; kk < 128; kk++) {
            float4 a = *(const float4*)&sph[kk * 64 + ty * 4];
            float avv[4] = {a.x, a.y, a.z, a.w};
            const float* br = sPW + kk * 192 + tx;
#pragma unroll
            for (int c = 0; c < 12; c++) {
                float bvv = br[c * 16];
#pragma unroll
                for (int i = 0; i < 4; i++) acc[i][c] += avv[i] * bvv;
            }
        }

#pragma unroll
        for (int i = 0; i < 4; i++) {
            int l = l0 + ty * 4 + i;
            float vr = 0.0f;
#pragma unroll
            for (int c = 0; c < 8; c++) vr += acc[i][c] * sph[(tx + 16*c) * 64 + ty * 4 + i];
            vr += __shfl_xor_sync(0xffffffffu, vr, 1);
            vr += __shfl_xor_sync(0xffffffffu, vr, 2);
            vr += __shfl_xor_sync(0xffffffffu, vr, 4);
            vr += __shfl_xor_sync(0xffffffffu, vr, 8);
            float stdv = sqrtf(fmaxf(sigma2 * vr, 0.0f));
            const float* erow = eps + ((size_t)bh * Ln + l) * DV;
            float* orow = g_sf + ((size_t)(b * Ln) + l) * HDIM + h * DV;
#pragma unroll
            for (int c = 0; c < 4; c++) {
                int d = tx + 16 * c;
                orow[d] = acc[i][8 + c] + stdv * erow[d];
            }
        }
    }
}

// ---------------- K8 ----------------
__global__ void k8_kl(float* __restrict__ out, int pos) {
    __shared__ float red[8];
    float s = 0.0f;
    for (int i = threadIdx.x; i < BH; i += 256) s += g_klbh[i];
    s = blk_sum(s, red);
    if (threadIdx.x == 0) out[pos] = s * (1.0f / (float)Bn);
}

// ---------------- launcher ----------------
extern "C" void kernel_launch(void* const* d_in, const int* in_sizes, int n_in,
                              void* d_out, int out_size) {
    const float* x          = (const float*)d_in[0];
    const float* W_qv       = (const float*)d_in[1];
    const float* log_sf     = (const float*)d_in[2];
    const float* log_ls     = (const float*)d_in[3];
    const float* log_sigma2 = (const float*)d_in[4];
    const float* omega_half = (const float*)d_in[5];
    const float* phase      = (const float*)d_in[6];
    const float* W_O_w      = (const float*)d_in[7];
    const float* W_O_b      = (const float*)d_in[8];
    const float* eps        = (const float*)d_in[9];
    float* out = (float*)d_out;

    const int TCSM = 4 * 32 * SSTR * 4;                       // 69,632 B
    const int GJSM = (128 * PIT + 8192 + 3 * 128 + 8) * 4;    // ~102 KB
    cudaFuncSetAttribute(gemm768_tc, cudaFuncAttributeMaxDynamicSharedMemorySize, TCSM);
    cudaFuncSetAttribute(k4_gj,      cudaFuncAttributeMaxDynamicSharedMemorySize, GJSM);
    cudaFuncSetAttribute(k56_mean,   cudaFuncAttributeMaxDynamicSharedMemorySize, 131072);

    k0_prep<<<192, 256>>>(log_sf, log_ls, omega_half);
    gemm768_tc<<<dim3(12, 256), 256, TCSM>>>(x, W_qv, 0, (const float*)0, (float*)0);
    k2_phi<<<dim3(16, BH), 256>>>(phase);
    k3_tc<<<BH, 256>>>();
    k4_gj<<<BH, 256, GJSM>>>(log_sigma2);
    k56_mean<<<dim3(4, BH), 256, 131072>>>(log_sigma2, eps);
    gemm768_tc<<<dim3(6, 256), 256, TCSM>>>((const float*)0, W_O_w, 1, W_O_b, out);
    k8_kl<<<1, 256>>>(out, out_size - 1);
}

// round 17
// speedup vs baseline: 1.8899x; 1.8899x over previous
#include <cuda_runtime.h>
#include <cuda_bf16.h>
#include <math.h>

#define Bn 32
#define Ln 1024
#define Hn 12
#define DV 64
#define MN 128
#define HDIM 768
#define BH (Bn*Hn)
#define TOK (Bn*Ln)
#define PIT 132

// ---------------- device scratch ----------------
__device__ float g_q  [BH*Ln*DV];
__device__ float g_v  [BH*Ln*DV];
__device__ float g_phi[BH*Ln*MN];
__device__ float g_om [Hn*DV*64];
__device__ float g_amp[Hn];
__device__ float g_G  [BH*MN*MN];
__device__ float g_C  [BH*MN*DV];
__device__ float g_P  [BH*MN*MN];
__device__ float g_W  [BH*MN*DV];
__device__ float g_sf [TOK*HDIM];
__device__ float g_klbh[BH];

__device__ __forceinline__ float blk_sum(float v, float* red) {
    int tid = threadIdx.x;
#pragma unroll
    for (int o = 16; o; o >>= 1) v += __shfl_xor_sync(0xffffffffu, v, o);
    __syncthreads();
    if ((tid & 31) == 0) red[tid >> 5] = v;
    __syncthreads();
    if (tid < 32) {
        float r = (tid < 8) ? red[tid] : 0.0f;
#pragma unroll
        for (int o = 4; o; o >>= 1) r += __shfl_xor_sync(0xffffffffu, r, o);
        if (tid == 0) red[0] = r;
    }
    __syncthreads();
    return red[0];
}

// ---------------- bf16 helpers ----------------
__device__ __forceinline__ unsigned pack2bf(float lo, float hi) {
    unsigned r;
    asm("cvt.rn.bf16x2.f32 %0, %1, %2;" : "=r"(r) : "f"(hi), "f"(lo));
    return r;
}
__device__ __forceinline__ void mma_bf16(float* d, const unsigned* a, const unsigned* b) {
    asm("mma.sync.aligned.m16n8k16.row.col.f32.bf16.bf16.f32 "
        "{%0,%1,%2,%3},{%4,%5,%6,%7},{%8,%9},{%0,%1,%2,%3};"
        : "+f"(d[0]), "+f"(d[1]), "+f"(d[2]), "+f"(d[3])
        : "r"(a[0]), "r"(a[1]), "r"(a[2]), "r"(a[3]), "r"(b[0]), "r"(b[1]));
}

// ---------------- K0 ----------------
__global__ void k0_prep(const float* __restrict__ log_sf,
                        const float* __restrict__ log_ls,
                        const float* __restrict__ omega_half) {
    int idx = blockIdx.x * blockDim.x + threadIdx.x;
    const int NOM = Hn * DV * 64;
    if (idx < NOM) {
        int h = idx / (DV * 64);
        int d = (idx / 64) % DV;
        float scale = 1.41421356237309515f * expf(-log_ls[h * DV + d]);
        g_om[idx] = omega_half[idx] * scale;
    }
    if (idx < Hn) g_amp[idx] = sqrtf(expf(log_sf[idx]));
}

// ---------------- gemm768_bf: out = A[rows,768] @ Wm[cols,768]^T via 3x bf16 m16n8k16 ----
#define SSTR 136
__global__ void __launch_bounds__(256) gemm768_bf(const float* __restrict__ Ain,
                                                  const float* __restrict__ Wm,
                                                  int mode,
                                                  const float* __restrict__ bias,
                                                  float* __restrict__ out) {
    extern __shared__ unsigned sm4[];
    unsigned* Ah = sm4;                 // 16 k2-rows x 128 rows (pitch SSTR)
    unsigned* Al = Ah + 16 * SSTR;
    unsigned* Bh = Al + 16 * SSTR;
    unsigned* Bl = Bh + 16 * SSTR;
    const float* A = (mode == 0) ? Ain : (const float*)g_sf;
    int cx = blockIdx.x, ry = blockIdx.y;
    int tid = threadIdx.x, lane = tid & 31, wid = tid >> 5;
    int m0 = (wid & 3) * 32, n0 = (wid >> 2) * 64;
    int lrow = tid >> 1, lk2 = (tid & 1) * 8;
    const float* ap = A  + (size_t)(ry * 128 + lrow) * HDIM + lk2 * 2;
    const float* bp = Wm + (size_t)(cx * 128 + lrow) * HDIM + lk2 * 2;

    float acc[2][8][4];
#pragma unroll
    for (int i = 0; i < 2; i++)
#pragma unroll
        for (int j = 0; j < 8; j++)
#pragma unroll
            for (int k = 0; k < 4; k++) acc[i][j][k] = 0.0f;

    float av[16], wv[16];
#pragma unroll
    for (int g = 0; g < 4; g++) {
        *(float4*)&av[g * 4] = *(const float4*)(ap + g * 4);
        *(float4*)&wv[g * 4] = *(const float4*)(bp + g * 4);
    }

    for (int c = 0; c < 24; c++) {
        __syncthreads();
#pragma unroll
        for (int i2 = 0; i2 < 8; i2++) {
            float a0f = av[2 * i2], a1f = av[2 * i2 + 1];
            float h0 = __bfloat162float(__float2bfloat16(a0f));
            float h1 = __bfloat162float(__float2bfloat16(a1f));
            Ah[(lk2 + i2) * SSTR + lrow] = pack2bf(h0, h1);
            Al[(lk2 + i2) * SSTR + lrow] = pack2bf(a0f - h0, a1f - h1);
            float w0f = wv[2 * i2], w1f = wv[2 * i2 + 1];
            float g0 = __bfloat162float(__float2bfloat16(w0f));
            float g1 = __bfloat162float(__float2bfloat16(w1f));
            Bh[(lk2 + i2) * SSTR + lrow] = pack2bf(g0, g1);
            Bl[(lk2 + i2) * SSTR + lrow] = pack2bf(w0f - g0, w1f - g1);
        }
        __syncthreads();
        if (c + 1 < 24) {
            const float* a2 = ap + (c + 1) * 32;
            const float* b2 = bp + (c + 1) * 32;
#pragma unroll
            for (int g = 0; g < 4; g++) {
                *(float4*)&av[g * 4] = *(const float4*)(a2 + g * 4);
                *(float4*)&wv[g * 4] = *(const float4*)(b2 + g * 4);
            }
        }
        int r = lane >> 2, q = lane & 3;
#pragma unroll
        for (int ks = 0; ks < 2; ks++) {
            int kc = ks * 8;
            unsigned ahi[2][4], alo[2][4];
#pragma unroll
            for (int mt = 0; mt < 2; mt++) {
                int mr = m0 + mt * 16 + r;
                ahi[mt][0] = Ah[(kc + q) * SSTR + mr];
                ahi[mt][1] = Ah[(kc + q) * SSTR + mr + 8];
                ahi[mt][2] = Ah[(kc + q + 4) * SSTR + mr];
                ahi[mt][3] = Ah[(kc + q + 4) * SSTR + mr + 8];
                alo[mt][0] = Al[(kc + q) * SSTR + mr];
                alo[mt][1] = Al[(kc + q) * SSTR + mr + 8];
                alo[mt][2] = Al[(kc + q + 4) * SSTR + mr];
                alo[mt][3] = Al[(kc + q + 4) * SSTR + mr + 8];
            }
#pragma unroll
            for (int nt = 0; nt < 8; nt++) {
                int nc = n0 + nt * 8 + r;
                unsigned bhi[2] = {Bh[(kc + q) * SSTR + nc], Bh[(kc + q + 4) * SSTR + nc]};
                unsigned blo[2] = {Bl[(kc + q) * SSTR + nc], Bl[(kc + q + 4) * SSTR + nc]};
#pragma unroll
                for (int mt = 0; mt < 2; mt++) {
                    mma_bf16(acc[mt][nt], ahi[mt], bhi);
                    mma_bf16(acc[mt][nt], ahi[mt], blo);
                    mma_bf16(acc[mt][nt], alo[mt], bhi);
                }
            }
        }
    }

    int r = lane >> 2, q = lane & 3;
#pragma unroll
    for (int mt = 0; mt < 2; mt++) {
#pragma unroll
        for (int nt = 0; nt < 8; nt++) {
            int cl = n0 + nt * 8 + 2 * q;
#pragma unroll
            for (int half = 0; half < 2; half++) {
                int row = ry * 128 + m0 + mt * 16 + r + half * 8;
                float c0 = acc[mt][nt][half * 2], c1 = acc[mt][nt][half * 2 + 1];
                if (mode == 0) {
                    int b = row >> 10, l = row & 1023;
                    size_t base = ((size_t)(b * Hn + cx) * Ln + l) * DV;
                    if (cl < 64) *(float2*)&g_q[base + cl]      = make_float2(c0, c1);
                    else         *(float2*)&g_v[base + cl - 64] = make_float2(c0, c1);
                } else {
                    int col = cx * 128 + cl;
                    *(float2*)&out[(size_t)row * HDIM + col] =
                        make_float2(c0 + bias[col], c1 + bias[col + 1]);
                }
            }
        }
    }
}

// ---------------- K2: phi (fast sincos) ----------------
__global__ void __launch_bounds__(256) k2_phi(const float* __restrict__ phase) {
    __shared__ float qs[64][64];
    __shared__ float oms[64][64];
    int l0 = blockIdx.x * 64;
    int bh = blockIdx.y;
    int h  = bh % Hn;
    int tid = threadIdx.x;
    int tx = tid & 15, ty = tid >> 4;
    int r = tid >> 2;
    int cbase = (tid & 3) * 16;
    const float* qrow = g_q + ((size_t)bh * Ln + l0 + r) * DV;
    const float* orow = g_om + (size_t)h * DV * 64 + r * 64;
#pragma unroll
    for (int c = 0; c < 4; c++) {
        float4 qv4 = *(const float4*)(qrow + cbase + c * 4);
        qs[cbase + c*4 + 0][r] = qv4.x; qs[cbase + c*4 + 1][r] = qv4.y;
        qs[cbase + c*4 + 2][r] = qv4.z; qs[cbase + c*4 + 3][r] = qv4.w;
        *(float4*)&oms[r][cbase + c * 4] = *(const float4*)(orow + cbase + c * 4);
    }
    __syncthreads();
    float acc[4][4] = {};
#pragma unroll
    for (int kk = 0; kk < 64; kk++) {
        float4 a = *(const float4*)&qs[kk][ty * 4];
        float4 b = *(const float4*)&oms[kk][tx * 4];
        acc[0][0] += a.x*b.x; acc[0][1] += a.x*b.y; acc[0][2] += a.x*b.z; acc[0][3] += a.x*b.w;
        acc[1][0] += a.y*b.x; acc[1][1] += a.y*b.y; acc[1][2] += a.y*b.z; acc[1][3] += a.y*b.w;
        acc[2][0] += a.z*b.x; acc[2][1] += a.z*b.y; acc[2][2] += a.z*b.z; acc[2][3] += a.z*b.w;
        acc[3][0] += a.w*b.x; acc[3][1] += a.w*b.y; acc[3][2] += a.w*b.z; acc[3][3] += a.w*b.w;
    }
    float sc = g_amp[h] * 0.08838834764831845f;
#pragma unroll
    for (int i = 0; i < 4; i++) {
        int l = l0 + ty * 4 + i;
        float* pb = g_phi + ((size_t)bh * Ln + l) * MN;
#pragma unroll
        for (int j = 0; j < 4; j++) {
            int m = tx * 4 + j;
            float p = acc[i][j] + phase[h * 64 + m];
            float s, c;
            __sincosf(p, &s, &c);
            pb[m]      = sc * c;
            pb[m + 64] = sc * s;
        }
    }
}

// ---------------- K3 (fp32 fastest): G = phi^T phi, C = phi^T v ----------------
__global__ void __launch_bounds__(256) k3_gram() {
    __shared__ float As[16][128];
    __shared__ float Bs[16][64];
    int nb = blockIdx.x;
    int bh = blockIdx.y;
    int tid = threadIdx.x;
    int tx = tid & 15, ty = tid >> 4;
    float acc[8][4] = {};
    int ra = tid >> 4;
    int ca = (tid & 15) * 8;
    int cb = (tid & 15) * 4;
    for (int l0 = 0; l0 < Ln; l0 += 16) {
        const float* prow = g_phi + ((size_t)bh * Ln + l0 + ra) * MN;
        *(float4*)&As[ra][ca]     = *(const float4*)(prow + ca);
        *(float4*)&As[ra][ca + 4] = *(const float4*)(prow + ca + 4);
        if (nb < 2)
            *(float4*)&Bs[ra][cb] = *(const float4*)(prow + nb * 64 + cb);
        else
            *(float4*)&Bs[ra][cb] = *(const float4*)(g_v + ((size_t)bh * Ln + l0 + ra) * DV + cb);
        __syncthreads();
#pragma unroll
        for (int kk = 0; kk < 16; kk++) {
            float4 a0 = *(const float4*)&As[kk][ty * 8];
            float4 a1 = *(const float4*)&As[kk][ty * 8 + 4];
            float4 b  = *(const float4*)&Bs[kk][tx * 4];
            float avv[8] = {a0.x,a0.y,a0.z,a0.w,a1.x,a1.y,a1.z,a1.w};
            float bvv[4] = {b.x,b.y,b.z,b.w};
#pragma unroll
            for (int i = 0; i < 8; i++)
#pragma unroll
                for (int j = 0; j < 4; j++) acc[i][j] += avv[i] * bvv[j];
        }
        __syncthreads();
    }
#pragma unroll
    for (int i = 0; i < 8; i++) {
        int m = ty * 8 + i;
#pragma unroll
        for (int j = 0; j < 4; j++) {
            int n = tx * 4 + j;
            if (nb < 2) g_G[(size_t)bh * MN * MN + m * MN + nb * 64 + n] = acc[i][j];
            else        g_C[(size_t)bh * MN * DV + m * DV + n]           = acc[i][j];
        }
    }
}

// ---------------- K4 (Gauss-Jordan inverse, fully parallel) ----------------
__global__ void __launch_bounds__(256) k4_gj(const float* __restrict__ log_sigma2) {
    extern __shared__ float sm[];
    float* sA   = sm;                  // 128 x PIT
    float* sC   = sm + 128 * PIT;      // 128 x 64
    float* rowj = sC + 8192;           // 128
    float* colj = rowj + 128;          // 128
    float* sPiv = colj + 128;          // 128
    __shared__ float red[8];
    __shared__ float sp;
    int bh = blockIdx.x;
    int tid = threadIdx.x;
    float sigma2 = expf(log_sigma2[0]);

    for (int i = tid; i < 16384; i += 256) {
        int r = i >> 7, c = i & 127;
        float v = g_G[(size_t)bh * 16384 + i];
        if (r == c) v += sigma2 + 1e-6f;
        sA[r * PIT + c] = v;
    }
    for (int i = tid; i < 8192; i += 256) sC[i] = g_C[(size_t)bh * 8192 + i];
    __syncthreads();

    int mi = tid >> 1;
    int kb = (tid & 1) * 64;
    for (int j = 0; j < 128; j++) {
        if (tid < 128) {
            rowj[tid] = sA[j * PIT + tid];
            colj[tid] = sA[tid * PIT + j];
        }
        if (tid == 0) { float d = sA[j * PIT + j]; sPiv[j] = d; sp = 1.0f / d; }
        __syncthreads();
        float p = sp;
        if (mi == j) {
#pragma unroll
            for (int c = 0; c < 64; c += 4) {
                int k = kb + c;
                float4 rv = *(float4*)&rowj[k];
                float4 o = make_float4(rv.x * p, rv.y * p, rv.z * p, rv.w * p);
                if (j >= k && j < k + 4) {
                    if (j == k) o.x = p; else if (j == k+1) o.y = p;
                    else if (j == k+2) o.z = p; else o.w = p;
                }
                *(float4*)&sA[j * PIT + k] = o;
            }
        } else {
            float ci = colj[mi] * p;
#pragma unroll
            for (int c = 0; c < 64; c += 4) {
                int k = kb + c;
                float4 av = *(float4*)&sA[mi * PIT + k];
                float4 rv = *(float4*)&rowj[k];
                float4 o = make_float4(av.x - ci * rv.x, av.y - ci * rv.y,
                                       av.z - ci * rv.z, av.w - ci * rv.w);
                if (j >= k && j < k + 4) {
                    float nv = -ci;
                    if (j == k) o.x = nv; else if (j == k+1) o.y = nv;
                    else if (j == k+2) o.z = nv; else o.w = nv;
                }
                *(float4*)&sA[mi * PIT + k] = o;
            }
        }
        __syncthreads();
    }

    float ld = (tid < 128) ? logf(sPiv[tid]) : 0.0f;
    float logdetA = blk_sum(ld, red);
    float tr = (tid < 128) ? sA[tid * PIT + tid] : 0.0f;
    float tr_Ainv = blk_sum(tr, red);

    float mu = 0.0f;
    for (int g = tid; g < 2048; g += 256) {
        int m = g >> 4, d4 = (g & 15) * 4;
        float4 a = make_float4(0.f, 0.f, 0.f, 0.f);
        for (int k = 0; k < 128; k++) {
            float pm = sA[m * PIT + k];
            float4 cv = *(float4*)&sC[k * 64 + d4];
            a.x += pm * cv.x; a.y += pm * cv.y; a.z += pm * cv.z; a.w += pm * cv.w;
        }
        *(float4*)&g_W[(size_t)bh * 8192 + m * 64 + d4] = a;
        mu += a.x * a.x + a.y * a.y + a.z * a.z + a.w * a.w;
    }
    float mu_norm2 = blk_sum(mu, red);

    for (int i = tid; i < 16384; i += 256) {
        int r = i >> 7, c = i & 127;
        g_P[(size_t)bh * 16384 + i] = sA[r * PIT + c];
    }

    if (tid == 0) {
        float kl = 0.5f * (64.0f * sigma2 * tr_Ainv + mu_norm2 - 8192.0f
                           - 64.0f * (128.0f * logf(sigma2) - logdetA));
        g_klbh[bh] = kl;
    }
}

// ---------------- K56: Y = phi @ [P|W]; var; samples ----------------
__global__ void __launch_bounds__(256) k56_mean(const float* __restrict__ log_sigma2,
                                               const float* __restrict__ eps) {
    extern __shared__ float sm[];
    float* sPW = sm;            // 128x192
    float* sph = sm + 24576;    // 128x64 (m-major)
    int lq = blockIdx.x, bh = blockIdx.y;
    int b = bh / Hn, h = bh % Hn;
    int tid = threadIdx.x;
    int tx = tid & 15, ty = tid >> 4;
    float sigma2 = expf(log_sigma2[0]);
    const float* Pb = g_P + (size_t)bh * 16384;
    const float* Wb = g_W + (size_t)bh * 8192;

#pragma unroll
    for (int qq = 0; qq < 24; qq++) {
        int w = (tid + 256 * qq) * 4;
        int k = w / 192, c = w - k * 192;
        float4 val = (c < 128) ? *(const float4*)(Pb + k * 128 + c)
                               : *(const float4*)(Wb + k * 64 + (c - 128));
        *(float4*)(sPW + w) = val;
    }

    int pl = tid & 63, pm = (tid >> 6) * 32;
    for (int t4 = 0; t4 < 4; t4++) {
        __syncthreads();
        int l0 = lq * 256 + t4 * 64;
        const float* prow = g_phi + ((size_t)bh * Ln + l0 + pl) * MN + pm;
#pragma unroll
        for (int e = 0; e < 8; e++) {
            float4 pv = *(const float4*)(prow + e * 4);
            sph[(pm + e*4 + 0) * 64 + pl] = pv.x;
            sph[(pm + e*4 + 1) * 64 + pl] = pv.y;
            sph[(pm + e*4 + 2) * 64 + pl] = pv.z;
            sph[(pm + e*4 + 3) * 64 + pl] = pv.w;
        }
        __syncthreads();

        float acc[4][12] = {};
#pragma unroll 8
        for (int kk = 0; kk < 128; kk++) {
            float4 a = *(const float4*)&sph[kk * 64 + ty * 4];
            float avv[4] = {a.x, a.y, a.z, a.w};
            const float* br = sPW + kk * 192 + tx;
#pragma unroll
            for (int c = 0; c < 12; c++) {
                float bvv = br[c * 16];
#pragma unroll
                for (int i = 0; i < 4; i++) acc[i][c] += avv[i] * bvv;
            }
        }

#pragma unroll
        for (int i = 0; i < 4; i++) {
            int l = l0 + ty * 4 + i;
            float vr = 0.0f;
#pragma unroll
            for (int c = 0; c < 8; c++) vr += acc[i][c] * sph[(tx + 16*c) * 64 + ty * 4 + i];
            vr += __shfl_xor_sync(0xffffffffu, vr, 1);
            vr += __shfl_xor_sync(0xffffffffu, vr, 2);
            vr += __shfl_xor_sync(0xffffffffu, vr, 4);
            vr += __shfl_xor_sync(0xffffffffu, vr, 8);
            float stdv = sqrtf(fmaxf(sigma2 * vr, 0.0f));
            const float* erow = eps + ((size_t)bh * Ln + l) * DV;
            float* orow = g_sf + ((size_t)(b * Ln) + l) * HDIM + h * DV;
#pragma unroll
            for (int c = 0; c < 4; c++) {
                int d = tx + 16 * c;
                orow[d] = acc[i][8 + c] + stdv * erow[d];
            }
        }
    }
}

// ---------------- K8 ----------------
__global__ void k8_kl(float* __restrict__ out, int pos) {
    __shared__ float red[8];
    float s = 0.0f;
    for (int i = threadIdx.x; i < BH; i += 256) s += g_klbh[i];
    s = blk_sum(s, red);
    if (threadIdx.x == 0) out[pos] = s * (1.0f / (float)Bn);
}

// ---------------- launcher ----------------
extern "C" void kernel_launch(void* const* d_in, const int* in_sizes, int n_in,
                              void* d_out, int out_size) {
    const float* x          = (const float*)d_in[0];
    const float* W_qv       = (const float*)d_in[1];
    const float* log_sf     = (const float*)d_in[2];
    const float* log_ls     = (const float*)d_in[3];
    const float* log_sigma2 = (const float*)d_in[4];
    const float* omega_half = (const float*)d_in[5];
    const float* phase      = (const float*)d_in[6];
    const float* W_O_w      = (const float*)d_in[7];
    const float* W_O_b      = (const float*)d_in[8];
    const float* eps        = (const float*)d_in[9];
    float* out = (float*)d_out;

    const int TCSM = 4 * 16 * SSTR * 4;                       // 34,816 B
    const int GJSM = (128 * PIT + 8192 + 3 * 128 + 8) * 4;    // ~102 KB
    cudaFuncSetAttribute(gemm768_bf, cudaFuncAttributeMaxDynamicSharedMemorySize, TCSM);
    cudaFuncSetAttribute(k4_gj,      cudaFuncAttributeMaxDynamicSharedMemorySize, GJSM);
    cudaFuncSetAttribute(k56_mean,   cudaFuncAttributeMaxDynamicSharedMemorySize, 131072);

    k0_prep<<<192, 256>>>(log_sf, log_ls, omega_half);
    gemm768_bf<<<dim3(12, 256), 256, TCSM>>>(x, W_qv, 0, (const float*)0, (float*)0);
    k2_phi<<<dim3(16, BH), 256>>>(phase);
    k3_gram<<<dim3(3, BH), 256>>>();
    k4_gj<<<BH, 256, GJSM>>>(log_sigma2);
    k56_mean<<<dim3(4, BH), 256, 131072>>>(log_sigma2, eps);
    gemm768_bf<<<dim3(6, 256), 256, TCSM>>>((const float*)0, W_O_w, 1, W_O_b, out);
    k8_kl<<<1, 256>>>(out, out_size - 1);
}